// round 15
// baseline (speedup 1.0000x reference)
#include <cuda_runtime.h>
#include <cuda_bf16.h>
#include <cuda_fp16.h>
#include <cstdint>

// Problem constants
#define NN 50000      // nodes
#define NE 800000     // edges
#define HEADS 4
#define CH 64
#define F 256         // HEADS*CH == input dim for both layers

// GEMM tiling
#define BM 128
#define BN 128
#define BK 16
#define NT (F / BK)   // 16 k-tiles

// scan config
#define SCAN_NB 13    // ceil(NN / 4096)

// ---------------- scratch (device globals; no allocation allowed) ----------------
__device__ float  g_h[NN * F];      // post-GEMM features (fp32)
__device__ __half g_h16[NN * F];    // fp16 copy for the gather path
__device__ float  g_feat[NN * F];   // layer-1 output / layer-2 input
__device__ float2 g_Bs[F * F];      // pre-split weights: (tf32-hi, tf32-lo)
__device__ float  g_asrc[NN * HEADS];
__device__ float  g_adst[NN * HEADS];
__device__ int    g_cnt[NN];        // in-degree histogram
__device__ int    g_start[NN + 1];  // CSR row starts (by dst)
__device__ int    g_cursor[NN];     // scatter cursors
__device__ int    g_csr_src[NE];    // src node id per CSR slot
__device__ int    g_bsum[SCAN_NB];  // scan block sums
__device__ int    g_boff[SCAN_NB];  // scan block offsets

// ---------------- helpers ----------------
__device__ __forceinline__ float lrelu(float x) { return x > 0.f ? x : 0.2f * x; }
__device__ __forceinline__ float elu1(float x)  { return x > 0.f ? x : expf(x) - 1.f; }

// tf32 mma: D += A(16x8, row) * B(8x8, col), fp32 accum
__device__ __forceinline__ void mma_tf32(float* d, const uint32_t* a, const uint32_t* b) {
    asm volatile(
        "mma.sync.aligned.m16n8k8.row.col.f32.tf32.tf32.f32 "
        "{%0,%1,%2,%3}, {%4,%5,%6,%7}, {%8,%9}, {%0,%1,%2,%3};"
        : "+f"(d[0]), "+f"(d[1]), "+f"(d[2]), "+f"(d[3])
        : "r"(a[0]), "r"(a[1]), "r"(a[2]), "r"(a[3]), "r"(b[0]), "r"(b[1]));
}

// split fp32 into tf32 hi + tf32 lo (truncation; lo*lo term ~2^-22, dropped)
__device__ __forceinline__ void tf32_split(float f, uint32_t& hi, uint32_t& lo) {
    hi = __float_as_uint(f) & 0xFFFFE000u;
    float lf = f - __uint_as_float(hi);
    lo = __float_as_uint(lf) & 0xFFFFE000u;
}

// ---------------- B pre-split: g_Bs[k*F+n] = (hi, lo) of W[k][n] ----------------
__global__ void bsplit_kernel(const float* __restrict__ B) {
    int i = blockIdx.x * blockDim.x + threadIdx.x;
    if (i >= F * F) return;
    uint32_t hi, lo;
    tf32_split(B[i], hi, lo);
    g_Bs[i] = make_float2(__uint_as_float(hi), __uint_as_float(lo));
}

// ---------------- GEMM + fused attn -------------------------------------------------
// 128x128 block tile, BK=16, 256 threads (8 warps, 4x2), warp tile 32x64.
// A: fp32 SMEM, split in loop. B: PRE-SPLIT float2 SMEM (zero B-split ALU in loop).
// Double-buffered SMEM (1 barrier/iter); fused per-warp attention epilogue.
__global__ void __launch_bounds__(256, 2)
gemm_tf32_kernel(const float* __restrict__ A,
                 const float* __restrict__ att_src, const float* __restrict__ att_dst) {
    __shared__ float  As[2][BK * BM];   // 16 KB
    __shared__ float2 Bs[2][BK * BN];   // 32 KB  (total 48 KB)

    int tid  = threadIdx.x;
    int warp = tid >> 5;
    int lane = tid & 31;
    int wm = warp >> 1;              // 0..3
    int wn = warp & 1;               // 0..1
    int row0 = blockIdx.y * BM;
    int col0 = blockIdx.x * BN;
    int c = lane & 3;                // quad column
    int r = lane >> 2;               // quad row (0..7)

    float acc[2][8][4];
#pragma unroll
    for (int mt = 0; mt < 2; mt++)
#pragma unroll
        for (int nt = 0; nt < 8; nt++)
#pragma unroll
            for (int i = 0; i < 4; i++) acc[mt][nt][i] = 0.f;

    // ---- gmem load mapping ----
    int am = tid >> 1;               // A row within tile (0..127)
    int ak = (tid & 1) * 8;          // A k offset (0 or 8)
    int bk = tid >> 4;               // B k row (0..15)
    int bn = (tid & 15) * 8;         // B n offset (0..120, step 8)

    // B store offsets under swizzle n ^ ((bk&3)<<2):
    // j=0..3 -> [bn' + 4*m2, +3], j=4..7 -> [bn' + 4*(1^m2), +3]
    int m2  = bk & 1;
    int bnp = bn ^ (((bk >> 1) & 1) << 3);
    int bg0 = bk * BN + (bnp + 4 * m2);
    int bg1 = bk * BN + (bnp + 4 * (1 - m2));

    float4 pa0, pa1, pb0, pb1, pb2, pb3;
    {
        int grow = row0 + am;
        if (grow < NN) {
            pa0 = *(const float4*)&A[grow * F + ak];
            pa1 = *(const float4*)&A[grow * F + ak + 4];
        } else {
            pa0 = make_float4(0.f, 0.f, 0.f, 0.f);
            pa1 = pa0;
        }
        const float4* bp = (const float4*)&g_Bs[bk * F + col0 + bn];
        pb0 = bp[0]; pb1 = bp[1]; pb2 = bp[2]; pb3 = bp[3];
    }

    // store tile 0 into buffer 0
    {
        float av[8] = {pa0.x, pa0.y, pa0.z, pa0.w, pa1.x, pa1.y, pa1.z, pa1.w};
#pragma unroll
        for (int j = 0; j < 8; j++) {
            int kk = ak + j;
            As[0][kk * BM + (am ^ ((kk & 3) << 3))] = av[j];
        }
        float4* p0 = (float4*)&Bs[0][bg0];
        p0[0] = pb0; p0[1] = pb1;
        float4* p1 = (float4*)&Bs[0][bg1];
        p1[0] = pb2; p1[1] = pb3;
    }
    __syncthreads();

    for (int it = 0; it < NT; it++) {
        int cur = it & 1;

        // prefetch next tile into regs
        if (it + 1 < NT) {
            int kn = (it + 1) * BK;
            int grow = row0 + am;
            if (grow < NN) {
                pa0 = *(const float4*)&A[grow * F + kn + ak];
                pa1 = *(const float4*)&A[grow * F + kn + ak + 4];
            } else {
                pa0 = make_float4(0.f, 0.f, 0.f, 0.f);
                pa1 = pa0;
            }
            const float4* bp = (const float4*)&g_Bs[(kn + bk) * F + col0 + bn];
            pb0 = bp[0]; pb1 = bp[1]; pb2 = bp[2]; pb3 = bp[3];
        }

        // compute from buf[cur]: two k8 steps
#pragma unroll
        for (int k8 = 0; k8 < 2; k8++) {
            int kb = k8 * 8;
            uint32_t aH[2][4], aL[2][4];
#pragma unroll
            for (int mt = 0; mt < 2; mt++) {
                int m0 = wm * 32 + mt * 16;
                int xr  = (m0 + r) ^ (c << 3);
                int xr8 = (m0 + r + 8) ^ (c << 3);
                float f0 = As[cur][(kb + c) * BM + xr];
                float f1 = As[cur][(kb + c) * BM + xr8];
                float f2 = As[cur][(kb + c + 4) * BM + xr];
                float f3 = As[cur][(kb + c + 4) * BM + xr8];
                tf32_split(f0, aH[mt][0], aL[mt][0]);
                tf32_split(f1, aH[mt][1], aL[mt][1]);
                tf32_split(f2, aH[mt][2], aL[mt][2]);
                tf32_split(f3, aH[mt][3], aL[mt][3]);
            }
#pragma unroll
            for (int nt = 0; nt < 8; nt++) {
                int n_ = wn * 64 + nt * 8 + r;
                int xn = n_ ^ (c << 2);           // (k&3)==c for rows kb+c, kb+c+4
                float2 v0 = Bs[cur][(kb + c) * BN + xn];
                float2 v1 = Bs[cur][(kb + c + 4) * BN + xn];
                uint32_t bH[2], bL[2];
                bH[0] = __float_as_uint(v0.x); bL[0] = __float_as_uint(v0.y);
                bH[1] = __float_as_uint(v1.x); bL[1] = __float_as_uint(v1.y);
#pragma unroll
                for (int mt = 0; mt < 2; mt++) {
                    mma_tf32(acc[mt][nt], aH[mt], bH);
                    mma_tf32(acc[mt][nt], aH[mt], bL);
                    mma_tf32(acc[mt][nt], aL[mt], bH);
                }
            }
        }

        // store next tile into the other buffer; single barrier per iteration
        if (it + 1 < NT) {
            int nxt = cur ^ 1;
            float av[8] = {pa0.x, pa0.y, pa0.z, pa0.w, pa1.x, pa1.y, pa1.z, pa1.w};
#pragma unroll
            for (int j = 0; j < 8; j++) {
                int kk = ak + j;
                As[nxt][kk * BM + (am ^ ((kk & 3) << 3))] = av[j];
            }
            float4* p0 = (float4*)&Bs[nxt][bg0];
            p0[0] = pb0; p0[1] = pb1;
            float4* p1 = (float4*)&Bs[nxt][bg1];
            p1[0] = pb2; p1[1] = pb3;
            __syncthreads();
        }
    }

    // ---- epilogue: write g_h / g_h16, and fused attention coefficients ----
    int head = (col0 >> 6) + wn;           // this warp's head (warp tile = 1 head)
    const float* as_v = &att_src[head * CH];
    const float* ad_v = &att_dst[head * CH];

#pragma unroll
    for (int mt = 0; mt < 2; mt++) {
        int rb = row0 + wm * 32 + mt * 16 + r;
        float ssA = 0.f, sdA = 0.f;        // row rb
        float ssB = 0.f, sdB = 0.f;        // row rb+8
#pragma unroll
        for (int nt = 0; nt < 8; nt++) {
            int cb = col0 + wn * 64 + nt * 8 + 2 * c;
            if (rb < NN) {
                *(float2*)&g_h[rb * F + cb] = make_float2(acc[mt][nt][0], acc[mt][nt][1]);
                *(__half2*)&g_h16[rb * F + cb] = __floats2half2_rn(acc[mt][nt][0], acc[mt][nt][1]);
            }
            if (rb + 8 < NN) {
                *(float2*)&g_h[(rb + 8) * F + cb] = make_float2(acc[mt][nt][2], acc[mt][nt][3]);
                *(__half2*)&g_h16[(rb + 8) * F + cb] = __floats2half2_rn(acc[mt][nt][2], acc[mt][nt][3]);
            }
            int j0 = nt * 8 + 2 * c;       // column within head (0..63)
            float a0v = as_v[j0], a1v = as_v[j0 + 1];
            float d0v = ad_v[j0], d1v = ad_v[j0 + 1];
            ssA += acc[mt][nt][0] * a0v + acc[mt][nt][1] * a1v;
            sdA += acc[mt][nt][0] * d0v + acc[mt][nt][1] * d1v;
            ssB += acc[mt][nt][2] * a0v + acc[mt][nt][3] * a1v;
            sdB += acc[mt][nt][2] * d0v + acc[mt][nt][3] * d1v;
        }
#pragma unroll
        for (int o = 1; o <= 2; o <<= 1) {
            ssA += __shfl_xor_sync(0xffffffffu, ssA, o);
            sdA += __shfl_xor_sync(0xffffffffu, sdA, o);
            ssB += __shfl_xor_sync(0xffffffffu, ssB, o);
            sdB += __shfl_xor_sync(0xffffffffu, sdB, o);
        }
        if (c == 0) {
            if (rb < NN)     { g_asrc[rb * 4 + head] = ssA; g_adst[rb * 4 + head] = sdA; }
            if (rb + 8 < NN) { g_asrc[(rb + 8) * 4 + head] = ssB; g_adst[(rb + 8) * 4 + head] = sdB; }
        }
    }
}

// ---------------- CSR build ----------------
__global__ void hist_kernel(const int* __restrict__ dst) {
    int e = blockIdx.x * blockDim.x + threadIdx.x;
    if (e < NE) atomicAdd(&g_cnt[dst[e]], 1);
}

// multi-block scan, pass 1: block-local exclusive scan + block sums
__global__ void scan_part_kernel() {
    __shared__ int warp_sums[32];
    int tid = threadIdx.x;
    int lane = tid & 31;
    int wid = tid >> 5;
    int i = blockIdx.x * 4096 + tid * 4;
    int4 v = make_int4(0, 0, 0, 0);
    if (i < NN) v = *(const int4*)&g_cnt[i];     // NN % 4 == 0
    int t = v.x + v.y + v.z + v.w;
    int x = t;
#pragma unroll
    for (int o = 1; o < 32; o <<= 1) {
        int y = __shfl_up_sync(0xffffffffu, x, o);
        if (lane >= o) x += y;
    }
    if (lane == 31) warp_sums[wid] = x;
    __syncthreads();
    if (wid == 0) {
        int ws = warp_sums[lane];
#pragma unroll
        for (int o = 1; o < 32; o <<= 1) {
            int y = __shfl_up_sync(0xffffffffu, ws, o);
            if (lane >= o) ws += y;
        }
        warp_sums[lane] = ws;
    }
    __syncthreads();
    int excl = x - t + (wid > 0 ? warp_sums[wid - 1] : 0);
    if (i < NN) {
        int4 e4 = make_int4(excl, excl + v.x, excl + v.x + v.y, excl + v.x + v.y + v.z);
        *(int4*)&g_start[i] = e4;
    }
    if (tid == blockDim.x - 1) g_bsum[blockIdx.x] = excl + t;
}

// pass 2: scan of the 13 block sums (1 warp)
__global__ void scan_tops_kernel() {
    int lane = threadIdx.x;
    int v = (lane < SCAN_NB) ? g_bsum[lane] : 0;
    int x = v;
#pragma unroll
    for (int o = 1; o < 32; o <<= 1) {
        int y = __shfl_up_sync(0xffffffffu, x, o);
        if (lane >= o) x += y;
    }
    if (lane < SCAN_NB) g_boff[lane] = x - v;
    if (lane == 31) g_start[NN] = x;   // grand total
}

// pass 3: add block offsets; mirror to cursor
__global__ void scan_add_kernel() {
    int i = blockIdx.x * 4096 + threadIdx.x * 4;
    if (i >= NN) return;
    int off = g_boff[blockIdx.x];
    int4 e = *(int4*)&g_start[i];
    e.x += off; e.y += off; e.z += off; e.w += off;
    *(int4*)&g_start[i]  = e;
    *(int4*)&g_cursor[i] = e;
}

__global__ void scatter_kernel(const int* __restrict__ src,
                               const int* __restrict__ dst) {
    int e = blockIdx.x * blockDim.x + threadIdx.x;
    if (e >= NE) return;
    int d = dst[e];
    int p = atomicAdd(&g_cursor[d], 1);
    g_csr_src[p] = src[e];
}

// ---------------- fused aggregation: warp per dst node, register accumulators ------
// out[d] = elu( (wself*h[d] + sum_e w_e*h16[src_e]) / (wself + sum w_e + 1e-16) + bias )
__global__ void __launch_bounds__(256)
agg_kernel(const float* __restrict__ bias, float* __restrict__ outp, int toFeat) {
    int d = blockIdx.x * 8 + (threadIdx.x >> 5);
    if (d >= NN) return;
    int lane = threadIdx.x & 31;
    int h = lane >> 3;                      // head for this lane's 8 columns

    float adst_h = g_adst[d * 4 + h];
    float wself  = expf(lrelu(g_asrc[d * 4 + h] + adst_h));

    const float4* hp = (const float4*)&g_h[d * F + lane * 8];
    float4 a0 = hp[0], a1 = hp[1];
    float4 acc0 = make_float4(wself * a0.x, wself * a0.y, wself * a0.z, wself * a0.w);
    float4 acc1 = make_float4(wself * a1.x, wself * a1.y, wself * a1.z, wself * a1.w);
    float denom = wself;

    int s0 = g_start[d];
    int s1 = g_start[d + 1];

    for (int base = s0; base < s1; base += 32) {
        int cnt = min(32, s1 - base);
        int sidx = (lane < cnt) ? g_csr_src[base + lane] : 0;
        int nsub = (cnt + 7) >> 3;
        for (int sub = 0; sub < nsub; sub++) {
            int sw = __shfl_sync(0xffffffffu, sidx, sub * 8 + (lane & 7));
            float wl = expf(lrelu(g_asrc[sw * 4 + h] + adst_h));
            int jend = min(8, cnt - sub * 8);
#pragma unroll 4
            for (int j = 0; j < jend; j++) {
                int s  = __shfl_sync(0xffffffffu, sidx, sub * 8 + j);
                float w = __shfl_sync(0xffffffffu, wl, (lane & 24) + j);
                uint4 raw = *(const uint4*)&g_h16[s * F + lane * 8];
                float2 f0 = __half22float2(*(__half2*)&raw.x);
                float2 f1 = __half22float2(*(__half2*)&raw.y);
                float2 f2 = __half22float2(*(__half2*)&raw.z);
                float2 f3 = __half22float2(*(__half2*)&raw.w);
                acc0.x += w * f0.x; acc0.y += w * f0.y;
                acc0.z += w * f1.x; acc0.w += w * f1.y;
                acc1.x += w * f2.x; acc1.y += w * f2.y;
                acc1.z += w * f3.x; acc1.w += w * f3.y;
                denom += w;
            }
        }
    }

    float inv = 1.f / (denom + 1e-16f);
    float4 b0 = *(const float4*)&bias[lane * 8];
    float4 b1 = *(const float4*)&bias[lane * 8 + 4];
    acc0.x = elu1(acc0.x * inv + b0.x);
    acc0.y = elu1(acc0.y * inv + b0.y);
    acc0.z = elu1(acc0.z * inv + b0.z);
    acc0.w = elu1(acc0.w * inv + b0.w);
    acc1.x = elu1(acc1.x * inv + b1.x);
    acc1.y = elu1(acc1.y * inv + b1.y);
    acc1.z = elu1(acc1.z * inv + b1.z);
    acc1.w = elu1(acc1.w * inv + b1.w);

    float* dp = (toFeat ? g_feat : outp) + d * F + lane * 8;
    *(float4*)dp       = acc0;
    *(float4*)(dp + 4) = acc1;
}

// ---------------- launch ----------------
static void run_layer(const float* Ain,
                      const float* W, const float* att_src, const float* att_dst,
                      const float* bias, float* outp, int toFeat) {
    bsplit_kernel<<<(F * F + 255) / 256, 256>>>(W);
    dim3 gemmGrid(F / BN, (NN + BM - 1) / BM);
    gemm_tf32_kernel<<<gemmGrid, 256>>>(Ain, att_src, att_dst);
    agg_kernel<<<(NN + 7) / 8, 256>>>(bias, outp, toFeat);
}

extern "C" void kernel_launch(void* const* d_in, const int* in_sizes, int n_in,
                              void* d_out, int out_size) {
    const float* x        = (const float*)d_in[0];
    const int*   ei       = (const int*)  d_in[1];
    const float* W1       = (const float*)d_in[2];
    const float* att_src1 = (const float*)d_in[3];
    const float* att_dst1 = (const float*)d_in[4];
    const float* b1       = (const float*)d_in[5];
    const float* W2       = (const float*)d_in[6];
    const float* att_src2 = (const float*)d_in[7];
    const float* att_dst2 = (const float*)d_in[8];
    const float* b2       = (const float*)d_in[9];
    float* out = (float*)d_out;

    const int* src = ei;            // edge_index[0]
    const int* dst = ei + NE;       // edge_index[1]

    // CSR build (shared by both layers)
    void* cnt_ptr = nullptr;
    cudaGetSymbolAddress(&cnt_ptr, g_cnt);
    cudaMemsetAsync(cnt_ptr, 0, NN * sizeof(int));
    hist_kernel<<<(NE + 255) / 256, 256>>>(dst);
    scan_part_kernel<<<SCAN_NB, 1024>>>();
    scan_tops_kernel<<<1, 32>>>();
    scan_add_kernel<<<SCAN_NB, 1024>>>();
    scatter_kernel<<<(NE + 255) / 256, 256>>>(src, dst);

    // layer 2 input pointer (device global address, host-visible)
    void* feat_ptr = nullptr;
    cudaGetSymbolAddress(&feat_ptr, g_feat);

    // layer 1: x -> g_feat
    run_layer(x, W1, att_src1, att_dst1, b1, nullptr, 1);
    // layer 2: g_feat -> out
    run_layer((const float*)feat_ptr, W2, att_src2, att_dst2, b2, out, 0);
}